// round 9
// baseline (speedup 1.0000x reference)
#include <cuda_runtime.h>
#include <cstdint>

// Problem constants
#define B_ROWS 8192
#define DIN    768
#define DHID   16384
#define TOPK   32
#define NCAND  40     // candidate pool (margin over TOPK)
#define NLIST  16     // per-thread stripe list depth (64-elem stripe)
#define DCHUNK 128    // k-chunk for rescore staging
#define NCHUNK (DIN / DCHUNK)   // 6
#define KSPLIT 512    // hypothesis: ref = fl(chain[0..511] + chain[512..767])

// ---------------------------------------------------------------------------
// Device-global scratch (allocation-free rule: __device__ globals only)
// ---------------------------------------------------------------------------
__device__ float g_pre[(size_t)B_ROWS * DHID];    // 512 MiB: pre-activations
__device__ float g_WdecT[(size_t)DHID * DIN];     // 48 MiB: W_dec transposed

// ---------------------------------------------------------------------------
// Zero-fill output buffer
// ---------------------------------------------------------------------------
__global__ void zero_kernel(float* __restrict__ p, long long n) {
    long long i = (long long)blockIdx.x * blockDim.x + threadIdx.x;
    long long stride = (long long)gridDim.x * blockDim.x;
    long long n4 = n >> 2;
    float4* p4 = (float4*)p;
    float4 z = make_float4(0.f, 0.f, 0.f, 0.f);
    for (long long j = i; j < n4; j += stride) p4[j] = z;
    for (long long j = (n4 << 2) + i; j < n; j += stride) p[j] = 0.f;
}

// ---------------------------------------------------------------------------
// Transpose W_dec [DIN][DHID] -> g_WdecT [DHID][DIN]
// ---------------------------------------------------------------------------
__global__ void transpose_kernel(const float* __restrict__ W) {
    __shared__ float tile[32][33];
    int x  = blockIdx.x * 32 + threadIdx.x;
    int y0 = blockIdx.y * 32;
    #pragma unroll
    for (int j = threadIdx.y; j < 32; j += 8)
        tile[j][threadIdx.x] = W[(size_t)(y0 + j) * DHID + x];
    __syncthreads();
    int xo  = blockIdx.y * 32 + threadIdx.x;
    int yo0 = blockIdx.x * 32;
    #pragma unroll
    for (int j = threadIdx.y; j < 32; j += 8)
        g_WdecT[(size_t)(yo0 + j) * DIN + xo] = tile[threadIdx.x][j];
}

// ---------------------------------------------------------------------------
// FP32 NT GEMM (candidate SELECTION only — outputs never touch these values)
// ---------------------------------------------------------------------------
#define BM 128
#define BN 128
#define BK 16
#define TM 8
#define TN 8

__global__ __launch_bounds__(256, 2)
void gemm_nt_kernel(const float* __restrict__ A,
                    const float* __restrict__ Bw,
                    const float* __restrict__ bias) {
    __shared__ float As[2][BK][BM];
    __shared__ float Bs[2][BK][BN];

    const int tid = threadIdx.x;
    const int m0  = blockIdx.y * BM;
    const int n0  = blockIdx.x * BN;
    const int tx  = tid & 15;
    const int ty  = tid >> 4;

    float acc[TM][TN];
    #pragma unroll
    for (int i = 0; i < TM; i++)
        #pragma unroll
        for (int j = 0; j < TN; j++) acc[i][j] = 0.f;

    const int r0  = (tid      ) >> 2, kq0 = (tid      ) & 3;
    const int r1  = (tid + 256) >> 2, kq1 = (tid + 256) & 3;

    {
        float4 va0 = *(const float4*)&A [(size_t)(m0 + r0) * DIN + kq0 * 4];
        float4 vb0 = *(const float4*)&Bw[(size_t)(n0 + r0) * DIN + kq0 * 4];
        float4 va1 = *(const float4*)&A [(size_t)(m0 + r1) * DIN + kq1 * 4];
        float4 vb1 = *(const float4*)&Bw[(size_t)(n0 + r1) * DIN + kq1 * 4];
        As[0][kq0*4+0][r0] = va0.x; As[0][kq0*4+1][r0] = va0.y;
        As[0][kq0*4+2][r0] = va0.z; As[0][kq0*4+3][r0] = va0.w;
        Bs[0][kq0*4+0][r0] = vb0.x; Bs[0][kq0*4+1][r0] = vb0.y;
        Bs[0][kq0*4+2][r0] = vb0.z; Bs[0][kq0*4+3][r0] = vb0.w;
        As[0][kq1*4+0][r1] = va1.x; As[0][kq1*4+1][r1] = va1.y;
        As[0][kq1*4+2][r1] = va1.z; As[0][kq1*4+3][r1] = va1.w;
        Bs[0][kq1*4+0][r1] = vb1.x; Bs[0][kq1*4+1][r1] = vb1.y;
        Bs[0][kq1*4+2][r1] = vb1.z; Bs[0][kq1*4+3][r1] = vb1.w;
    }
    __syncthreads();

    const int nk = DIN / BK;
    for (int t = 0; t < nk; t++) {
        const int buf = t & 1;
        float4 ra0, ra1, rb0, rb1;
        const bool more = (t + 1 < nk);
        if (more) {
            const int kt = (t + 1) * BK;
            ra0 = *(const float4*)&A [(size_t)(m0 + r0) * DIN + kt + kq0 * 4];
            rb0 = *(const float4*)&Bw[(size_t)(n0 + r0) * DIN + kt + kq0 * 4];
            ra1 = *(const float4*)&A [(size_t)(m0 + r1) * DIN + kt + kq1 * 4];
            rb1 = *(const float4*)&Bw[(size_t)(n0 + r1) * DIN + kt + kq1 * 4];
        }

        #pragma unroll
        for (int k = 0; k < BK; k++) {
            float4 a0 = *(const float4*)&As[buf][k][ty * TM];
            float4 a1 = *(const float4*)&As[buf][k][ty * TM + 4];
            float4 b0 = *(const float4*)&Bs[buf][k][tx * TN];
            float4 b1 = *(const float4*)&Bs[buf][k][tx * TN + 4];
            float av[TM] = {a0.x, a0.y, a0.z, a0.w, a1.x, a1.y, a1.z, a1.w};
            float bv[TN] = {b0.x, b0.y, b0.z, b0.w, b1.x, b1.y, b1.z, b1.w};
            #pragma unroll
            for (int i = 0; i < TM; i++)
                #pragma unroll
                for (int j = 0; j < TN; j++)
                    acc[i][j] = fmaf(av[i], bv[j], acc[i][j]);
        }

        if (more) {
            const int nb = (t + 1) & 1;
            As[nb][kq0*4+0][r0] = ra0.x; As[nb][kq0*4+1][r0] = ra0.y;
            As[nb][kq0*4+2][r0] = ra0.z; As[nb][kq0*4+3][r0] = ra0.w;
            Bs[nb][kq0*4+0][r0] = rb0.x; Bs[nb][kq0*4+1][r0] = rb0.y;
            Bs[nb][kq0*4+2][r0] = rb0.z; Bs[nb][kq0*4+3][r0] = rb0.w;
            As[nb][kq1*4+0][r1] = ra1.x; As[nb][kq1*4+1][r1] = ra1.y;
            As[nb][kq1*4+2][r1] = ra1.z; As[nb][kq1*4+3][r1] = ra1.w;
            Bs[nb][kq1*4+0][r1] = rb1.x; Bs[nb][kq1*4+1][r1] = rb1.y;
            Bs[nb][kq1*4+2][r1] = rb1.z; Bs[nb][kq1*4+3][r1] = rb1.w;
        }
        __syncthreads();
    }

    const float4 bb0 = *(const float4*)&bias[n0 + tx * TN];
    const float4 bb1 = *(const float4*)&bias[n0 + tx * TN + 4];
    #pragma unroll
    for (int i = 0; i < TM; i++) {
        const int gm = m0 + ty * TM + i;
        float* cptr = &g_pre[(size_t)gm * DHID + n0 + tx * TN];
        float4 v0 = make_float4(acc[i][0] + bb0.x, acc[i][1] + bb0.y,
                                acc[i][2] + bb0.z, acc[i][3] + bb0.w);
        float4 v1 = make_float4(acc[i][4] + bb1.x, acc[i][5] + bb1.y,
                                acc[i][6] + bb1.z, acc[i][7] + bb1.w);
        *(float4*)(cptr)     = v0;
        *(float4*)(cptr + 4) = v1;
    }
}

// ---------------------------------------------------------------------------
// Error-free transforms (intrinsics so contraction can't destroy them)
// ---------------------------------------------------------------------------
__device__ __forceinline__ void two_sum(float a, float b, float& s, float& e) {
    s = __fadd_rn(a, b);
    float bv = __fsub_rn(s, a);
    e = __fadd_rn(__fsub_rn(a, __fsub_rn(s, bv)), __fsub_rn(b, bv));
}

__device__ __forceinline__ unsigned long long make_key(float v, int h) {
    unsigned int u = __float_as_uint(v);
    unsigned int e = (u & 0x80000000u) ? ~u : (u | 0x80000000u);
    return ((unsigned long long)e << 32) | (unsigned int)(0xFFFFFFFFu - (unsigned int)h);
}

// ---------------------------------------------------------------------------
// Fused: candidate top-40 selection -> dual rescore:
//   EXACT (compensated)  -> decides top-32 MEMBERSHIP (matched ref 5x)
//   HYPOTHESIS: hval = fl( fma-chain(k=0..511) + fma-chain(k=512..767) ) + b
//               -> decides internal ORDER and output values
// Then scatter + idx output + decode.
// ---------------------------------------------------------------------------
__global__ __launch_bounds__(256)
void topk_rescore_decode_kernel(const float* __restrict__ x,
                                const float* __restrict__ W_enc,
                                const float* __restrict__ b_enc,
                                const float* __restrict__ b_dec,
                                float* __restrict__ recon,
                                float* __restrict__ sparse,
                                float* __restrict__ idxout) {
    const int b   = blockIdx.x;
    const int tid = threadIdx.x;
    const int lane = tid & 31, wid = tid >> 5;
    const float* row = g_pre + (size_t)b * DHID;

    __shared__ float s_x[DIN];
    __shared__ float s_w[NCAND][DCHUNK + 1];
    __shared__ unsigned long long s_wmax[8];
    __shared__ unsigned long long s_sel;
    __shared__ int   s_cidx[NCAND];
    __shared__ float s_hval[NCAND];                  // hypothesis values
    __shared__ unsigned long long s_ekey[NCAND];     // exact keys (membership)
    __shared__ unsigned long long s_hkey[NCAND];     // hypothesis keys (order)
    __shared__ int   s_member[NCAND];
    __shared__ float s_val[TOPK];
    __shared__ int   s_idx[TOPK];

    for (int i = tid; i < DIN; i += 256) s_x[i] = x[(size_t)b * DIN + i];

    // --- Phase 1: per-thread top-16 of its 64-element stripe ---
    unsigned long long list[NLIST];
    #pragma unroll
    for (int i = 0; i < NLIST; i++) list[i] = 0ULL;

    for (int j = 0; j < DHID / 256; j++) {
        const int h = tid + j * 256;
        unsigned long long key = make_key(row[h], h);
        if (key > list[NLIST - 1]) {
            int p = NLIST - 1;
            #pragma unroll
            for (int q = NLIST - 1; q > 0; q--) {
                if (list[q - 1] < key) { list[q] = list[q - 1]; p = q - 1; }
            }
            list[p] = key;
        }
    }

    // --- Phase 2: block tournament for top-NCAND candidates ---
    int ptr = 0;
    for (int k = 0; k < NCAND; k++) {
        unsigned long long h = (ptr < NLIST) ? list[ptr] : 0ULL;
        unsigned long long m = h;
        #pragma unroll
        for (int off = 16; off > 0; off >>= 1) {
            unsigned long long o = __shfl_down_sync(0xFFFFFFFFu, m, off);
            if (o > m) m = o;
        }
        if (lane == 0) s_wmax[wid] = m;
        __syncthreads();
        if (tid == 0) {
            unsigned long long g = s_wmax[0];
            #pragma unroll
            for (int w = 1; w < 8; w++) if (s_wmax[w] > g) g = s_wmax[w];
            s_sel = g;
            s_cidx[k] = (int)(0xFFFFFFFFu - (unsigned int)g);
        }
        __syncthreads();
        if (h == s_sel) ptr++;
    }

    // --- Phase 3: dual rescore, one thread per candidate, ascending k ---
    // HYPOTHESIS: lo = fma-chain k=0..511; hi = fma-chain k=512..767;
    //             hval = fl(fl(lo + hi) + b_enc)
    float lo_acc = 0.f, hi_acc = 0.f;
    float ex_hi = 0.f, ex_lo = 0.f;   // exact: compensated
    for (int ch = 0; ch < NCHUNK; ch++) {
        for (int q = tid; q < NCAND * (DCHUNK / 4); q += 256) {
            const int c  = q / (DCHUNK / 4);
            const int kq = q % (DCHUNK / 4);
            const float4 v = *(const float4*)&W_enc[(size_t)s_cidx[c] * DIN
                                                    + ch * DCHUNK + kq * 4];
            s_w[c][kq * 4 + 0] = v.x;
            s_w[c][kq * 4 + 1] = v.y;
            s_w[c][kq * 4 + 2] = v.z;
            s_w[c][kq * 4 + 3] = v.w;
        }
        __syncthreads();
        if (tid < NCAND) {
            if (ch * DCHUNK < KSPLIT) {
                #pragma unroll 4
                for (int kk = 0; kk < DCHUNK; kk++) {
                    const float xv = s_x[ch * DCHUNK + kk];
                    const float wv = s_w[tid][kk];
                    lo_acc = __fmaf_rn(xv, wv, lo_acc);
                    const float p = __fmul_rn(xv, wv);
                    const float e = __fmaf_rn(xv, wv, -p);
                    float s, err;
                    two_sum(ex_hi, p, s, err);
                    ex_hi = s;
                    ex_lo = __fadd_rn(ex_lo, __fadd_rn(e, err));
                }
            } else {
                #pragma unroll 4
                for (int kk = 0; kk < DCHUNK; kk++) {
                    const float xv = s_x[ch * DCHUNK + kk];
                    const float wv = s_w[tid][kk];
                    hi_acc = __fmaf_rn(xv, wv, hi_acc);
                    const float p = __fmul_rn(xv, wv);
                    const float e = __fmaf_rn(xv, wv, -p);
                    float s, err;
                    two_sum(ex_hi, p, s, err);
                    ex_hi = s;
                    ex_lo = __fadd_rn(ex_lo, __fadd_rn(e, err));
                }
            }
        }
        __syncthreads();
    }
    if (tid < NCAND) {
        const int idx = s_cidx[tid];
        const float bb = b_enc[idx];
        // hypothesis value: combine the two block-chains, then bias
        const float hv = __fadd_rn(__fadd_rn(lo_acc, hi_acc), bb);
        // exact value: compensated + bias, rounded to fp32
        float s, err;
        two_sum(ex_hi, bb, s, err);
        const float ev = __fadd_rn(s, __fadd_rn(ex_lo, err));
        s_hval[tid] = hv;
        s_ekey[tid] = make_key(ev, idx);
        s_hkey[tid] = make_key(hv, idx);
    }
    __syncthreads();

    // --- Phase 4: membership by EXACT rank; order by HYPOTHESIS rank ---
    if (tid < NCAND) {
        const unsigned long long ek = s_ekey[tid];
        int erank = 0;
        #pragma unroll
        for (int j = 0; j < NCAND; j++) erank += (s_ekey[j] > ek) ? 1 : 0;
        s_member[tid] = (erank < TOPK) ? 1 : 0;
    }
    __syncthreads();
    if (tid < NCAND && s_member[tid]) {
        const unsigned long long hk = s_hkey[tid];
        const int idx = s_cidx[tid];
        int hrank = 0;
        #pragma unroll
        for (int j = 0; j < NCAND; j++)
            if (s_member[j]) hrank += (s_hkey[j] > hk) ? 1 : 0;
        const float rv = fmaxf(s_hval[tid], 0.0f);
        if (idxout) idxout[(size_t)b * TOPK + hrank] = (float)idx;
        if (sparse) sparse[(size_t)b * DHID + idx] = rv;
        s_val[hrank] = rv;
        s_idx[hrank] = idx;
    }
    __syncthreads();

    // --- Phase 5: decode recon[b,:] = b_dec + sum_j val_j * WdecT[idx_j,:] ---
    for (int i = tid; i < DIN; i += 256) {
        float acc = b_dec[i];
        #pragma unroll
        for (int j = 0; j < TOPK; j++)
            acc = fmaf(s_val[j], g_WdecT[(size_t)s_idx[j] * DIN + i], acc);
        recon[(size_t)b * DIN + i] = acc;
    }
}

// ---------------------------------------------------------------------------
// Launch
// ---------------------------------------------------------------------------
extern "C" void kernel_launch(void* const* d_in, const int* in_sizes, int n_in,
                              void* d_out, int out_size) {
    const float* x     = (const float*)d_in[0];
    const float* W_enc = (const float*)d_in[1];
    const float* b_enc = (const float*)d_in[2];
    const float* W_dec = (const float*)d_in[3];
    const float* b_dec = (const float*)d_in[4];
    float* out = (float*)d_out;

    const long long n_recon  = (long long)B_ROWS * DIN;
    const long long n_sparse = (long long)B_ROWS * DHID;
    const long long n_idx    = (long long)B_ROWS * TOPK;
    const long long osz = (long long)out_size;

    float* recon  = out;
    float* sparse = (osz >= n_recon + n_sparse)         ? out + n_recon            : nullptr;
    float* idxo   = (osz >= n_recon + n_sparse + n_idx) ? out + n_recon + n_sparse : nullptr;

    zero_kernel<<<4096, 256>>>(out, osz);
    transpose_kernel<<<dim3(DHID / 32, DIN / 32), dim3(32, 8)>>>(W_dec);
    gemm_nt_kernel<<<dim3(DHID / BN, B_ROWS / BM), 256>>>(x, W_enc, b_enc);
    topk_rescore_decode_kernel<<<B_ROWS, 256>>>(x, W_enc, b_enc, b_dec,
                                                recon, sparse, idxo);
}

// round 10
// speedup vs baseline: 1.6411x; 1.6411x over previous
#include <cuda_runtime.h>
#include <cstdint>

// Problem constants
#define B_ROWS 8192
#define DIN    768
#define DHID   16384
#define TOPK   32
#define NCAND  40     // candidate pool (margin over TOPK)
#define NLIST  16     // per-thread stripe list depth (64-elem stripe)
#define DCHUNK 128    // k-chunk for rescore staging
#define NCHUNK (DIN / DCHUNK)   // 6
#define KSPLIT 512    // ref = fl(chain[0..511] + chain[512..767])  (CONFIRMED R9)

// ---------------------------------------------------------------------------
// Device-global scratch (allocation-free rule: __device__ globals only)
// ---------------------------------------------------------------------------
__device__ float g_pre[(size_t)B_ROWS * DHID];    // 512 MiB: selection scores
__device__ float g_WdecT[(size_t)DHID * DIN];     // 48 MiB: W_dec transposed

// ---------------------------------------------------------------------------
// Zero-fill output buffer
// ---------------------------------------------------------------------------
__global__ void zero_kernel(float* __restrict__ p, long long n) {
    long long i = (long long)blockIdx.x * blockDim.x + threadIdx.x;
    long long stride = (long long)gridDim.x * blockDim.x;
    long long n4 = n >> 2;
    float4* p4 = (float4*)p;
    float4 z = make_float4(0.f, 0.f, 0.f, 0.f);
    for (long long j = i; j < n4; j += stride) p4[j] = z;
    for (long long j = (n4 << 2) + i; j < n; j += stride) p[j] = 0.f;
}

// ---------------------------------------------------------------------------
// Transpose W_dec [DIN][DHID] -> g_WdecT [DHID][DIN]
// ---------------------------------------------------------------------------
__global__ void transpose_kernel(const float* __restrict__ W) {
    __shared__ float tile[32][33];
    int x  = blockIdx.x * 32 + threadIdx.x;
    int y0 = blockIdx.y * 32;
    #pragma unroll
    for (int j = threadIdx.y; j < 32; j += 8)
        tile[j][threadIdx.x] = W[(size_t)(y0 + j) * DHID + x];
    __syncthreads();
    int xo  = blockIdx.y * 32 + threadIdx.x;
    int yo0 = blockIdx.x * 32;
    #pragma unroll
    for (int j = threadIdx.y; j < 32; j += 8)
        g_WdecT[(size_t)(yo0 + j) * DIN + xo] = tile[threadIdx.x][j];
}

// ---------------------------------------------------------------------------
// TF32 tensor-core NT GEMM (candidate SELECTION only — outputs never touch
// these values; true top-32 vs top-40 pool margin is ~80 sigma of tf32 noise)
//   g_pre[m][n] = dot(x[m,:], W_enc[n,:]) + b_enc[n]
// 128x128 tile, BK=16, 8 warps of 64x32, mma.sync.m16n8k8.tf32
// ---------------------------------------------------------------------------
#define BM 128
#define BN 128
#define BK 16
#define SSTR 20   // smem row stride in floats (conflict-free for frag reads)

__device__ __forceinline__ uint32_t f2tf32(float f) {
    uint32_t r;
    asm("cvt.rna.tf32.f32 %0, %1;" : "=r"(r) : "f"(f));
    return r;
}

__device__ __forceinline__ void mma_tf32(float c[4],
                                         uint32_t a0, uint32_t a1,
                                         uint32_t a2, uint32_t a3,
                                         uint32_t b0, uint32_t b1) {
    asm volatile(
        "mma.sync.aligned.m16n8k8.row.col.f32.tf32.tf32.f32 "
        "{%0,%1,%2,%3}, {%4,%5,%6,%7}, {%8,%9}, {%0,%1,%2,%3};\n"
        : "+f"(c[0]), "+f"(c[1]), "+f"(c[2]), "+f"(c[3])
        : "r"(a0), "r"(a1), "r"(a2), "r"(a3), "r"(b0), "r"(b1));
}

__global__ __launch_bounds__(256, 2)
void gemm_tf32_kernel(const float* __restrict__ A,   // [B_ROWS][DIN]
                      const float* __restrict__ Bw,  // [DHID][DIN]
                      const float* __restrict__ bias) {
    __shared__ uint32_t sA[2][BM * SSTR];
    __shared__ uint32_t sB[2][BN * SSTR];

    const int tid = threadIdx.x;
    const int m0  = blockIdx.y * BM;
    const int n0  = blockIdx.x * BN;

    const int warp   = tid >> 5;
    const int lane   = tid & 31;
    const int g      = lane >> 2;    // groupID (0..7)
    const int tig    = lane & 3;     // thread-in-group (0..3)
    const int warp_m = warp & 1;     // 0..1  -> 64 rows each
    const int warp_n = warp >> 1;    // 0..3  -> 32 cols each

    float acc[4][4][4];
    #pragma unroll
    for (int i = 0; i < 4; i++)
        #pragma unroll
        for (int j = 0; j < 4; j++)
            #pragma unroll
            for (int r = 0; r < 4; r++) acc[i][j][r] = 0.f;

    // Global tile loaders: 512 float4 per operand per tile, 2 per thread
    const int r0  = (tid      ) >> 2, kq0 = (tid      ) & 3;
    const int r1  = (tid + 256) >> 2, kq1 = (tid + 256) & 3;

    // Prologue: load tile 0
    {
        float4 va0 = *(const float4*)&A [(size_t)(m0 + r0) * DIN + kq0 * 4];
        float4 vb0 = *(const float4*)&Bw[(size_t)(n0 + r0) * DIN + kq0 * 4];
        float4 va1 = *(const float4*)&A [(size_t)(m0 + r1) * DIN + kq1 * 4];
        float4 vb1 = *(const float4*)&Bw[(size_t)(n0 + r1) * DIN + kq1 * 4];
        uint32_t* pa0 = &sA[0][r0 * SSTR + kq0 * 4];
        uint32_t* pb0 = &sB[0][r0 * SSTR + kq0 * 4];
        uint32_t* pa1 = &sA[0][r1 * SSTR + kq1 * 4];
        uint32_t* pb1 = &sB[0][r1 * SSTR + kq1 * 4];
        pa0[0]=f2tf32(va0.x); pa0[1]=f2tf32(va0.y); pa0[2]=f2tf32(va0.z); pa0[3]=f2tf32(va0.w);
        pb0[0]=f2tf32(vb0.x); pb0[1]=f2tf32(vb0.y); pb0[2]=f2tf32(vb0.z); pb0[3]=f2tf32(vb0.w);
        pa1[0]=f2tf32(va1.x); pa1[1]=f2tf32(va1.y); pa1[2]=f2tf32(va1.z); pa1[3]=f2tf32(va1.w);
        pb1[0]=f2tf32(vb1.x); pb1[1]=f2tf32(vb1.y); pb1[2]=f2tf32(vb1.z); pb1[3]=f2tf32(vb1.w);
    }
    __syncthreads();

    const int nk = DIN / BK;   // 48
    for (int t = 0; t < nk; t++) {
        const int buf = t & 1;
        float4 ra0, ra1, rb0, rb1;
        const bool more = (t + 1 < nk);
        if (more) {
            const int kt = (t + 1) * BK;
            ra0 = *(const float4*)&A [(size_t)(m0 + r0) * DIN + kt + kq0 * 4];
            rb0 = *(const float4*)&Bw[(size_t)(n0 + r0) * DIN + kt + kq0 * 4];
            ra1 = *(const float4*)&A [(size_t)(m0 + r1) * DIN + kt + kq1 * 4];
            rb1 = *(const float4*)&Bw[(size_t)(n0 + r1) * DIN + kt + kq1 * 4];
        }

        const uint32_t* As = sA[buf];
        const uint32_t* Bs = sB[buf];
        #pragma unroll
        for (int ks = 0; ks < BK; ks += 8) {
            // B fragments for 4 n-tiles
            uint32_t bf0[4], bf1[4];
            #pragma unroll
            for (int j = 0; j < 4; j++) {
                const int nb = warp_n * 32 + j * 8 + g;
                bf0[j] = Bs[nb * SSTR + ks + tig];
                bf1[j] = Bs[nb * SSTR + ks + tig + 4];
            }
            #pragma unroll
            for (int i = 0; i < 4; i++) {
                const int mb = warp_m * 64 + i * 16;
                const uint32_t a0 = As[(mb + g    ) * SSTR + ks + tig    ];
                const uint32_t a1 = As[(mb + g + 8) * SSTR + ks + tig    ];
                const uint32_t a2 = As[(mb + g    ) * SSTR + ks + tig + 4];
                const uint32_t a3 = As[(mb + g + 8) * SSTR + ks + tig + 4];
                #pragma unroll
                for (int j = 0; j < 4; j++)
                    mma_tf32(acc[i][j], a0, a1, a2, a3, bf0[j], bf1[j]);
            }
        }

        if (more) {
            const int nb = (t + 1) & 1;
            uint32_t* pa0 = &sA[nb][r0 * SSTR + kq0 * 4];
            uint32_t* pb0 = &sB[nb][r0 * SSTR + kq0 * 4];
            uint32_t* pa1 = &sA[nb][r1 * SSTR + kq1 * 4];
            uint32_t* pb1 = &sB[nb][r1 * SSTR + kq1 * 4];
            pa0[0]=f2tf32(ra0.x); pa0[1]=f2tf32(ra0.y); pa0[2]=f2tf32(ra0.z); pa0[3]=f2tf32(ra0.w);
            pb0[0]=f2tf32(rb0.x); pb0[1]=f2tf32(rb0.y); pb0[2]=f2tf32(rb0.z); pb0[3]=f2tf32(rb0.w);
            pa1[0]=f2tf32(ra1.x); pa1[1]=f2tf32(ra1.y); pa1[2]=f2tf32(ra1.z); pa1[3]=f2tf32(ra1.w);
            pb1[0]=f2tf32(rb1.x); pb1[1]=f2tf32(rb1.y); pb1[2]=f2tf32(rb1.z); pb1[3]=f2tf32(rb1.w);
        }
        __syncthreads();
    }

    // Epilogue: add bias, store (float2 per fragment row-pair)
    #pragma unroll
    for (int j = 0; j < 4; j++) {
        const int col = n0 + warp_n * 32 + j * 8 + 2 * tig;
        const float2 bb = *(const float2*)&bias[col];
        #pragma unroll
        for (int i = 0; i < 4; i++) {
            const int row = m0 + warp_m * 64 + i * 16 + g;
            float2 v0 = make_float2(acc[i][j][0] + bb.x, acc[i][j][1] + bb.y);
            float2 v1 = make_float2(acc[i][j][2] + bb.x, acc[i][j][3] + bb.y);
            *(float2*)&g_pre[(size_t)row * DHID + col]       = v0;
            *(float2*)&g_pre[(size_t)(row + 8) * DHID + col] = v1;
        }
    }
}

// ---------------------------------------------------------------------------
// Error-free transforms (intrinsics so contraction can't destroy them)
// ---------------------------------------------------------------------------
__device__ __forceinline__ void two_sum(float a, float b, float& s, float& e) {
    s = __fadd_rn(a, b);
    float bv = __fsub_rn(s, a);
    e = __fadd_rn(__fsub_rn(a, __fsub_rn(s, bv)), __fsub_rn(b, bv));
}

__device__ __forceinline__ unsigned long long make_key(float v, int h) {
    unsigned int u = __float_as_uint(v);
    unsigned int e = (u & 0x80000000u) ? ~u : (u | 0x80000000u);
    return ((unsigned long long)e << 32) | (unsigned int)(0xFFFFFFFFu - (unsigned int)h);
}

// ---------------------------------------------------------------------------
// Fused: candidate top-40 selection -> dual rescore:
//   EXACT (compensated)  -> decides top-32 MEMBERSHIP
//   REF-CHAIN: hval = fl( fma-chain(0..511) + fma-chain(512..767) ) + b
//              -> decides internal ORDER and output values   (CONFIRMED)
// Then scatter + idx output + decode.
// ---------------------------------------------------------------------------
__global__ __launch_bounds__(256)
void topk_rescore_decode_kernel(const float* __restrict__ x,
                                const float* __restrict__ W_enc,
                                const float* __restrict__ b_enc,
                                const float* __restrict__ b_dec,
                                float* __restrict__ recon,
                                float* __restrict__ sparse,
                                float* __restrict__ idxout) {
    const int b   = blockIdx.x;
    const int tid = threadIdx.x;
    const int lane = tid & 31, wid = tid >> 5;
    const float* row = g_pre + (size_t)b * DHID;

    __shared__ float s_x[DIN];
    __shared__ float s_w[NCAND][DCHUNK + 1];
    __shared__ unsigned long long s_wmax[8];
    __shared__ unsigned long long s_sel;
    __shared__ int   s_cidx[NCAND];
    __shared__ float s_hval[NCAND];                  // ref-chain values
    __shared__ unsigned long long s_ekey[NCAND];     // exact keys (membership)
    __shared__ unsigned long long s_hkey[NCAND];     // ref-chain keys (order)
    __shared__ int   s_member[NCAND];
    __shared__ float s_val[TOPK];
    __shared__ int   s_idx[TOPK];

    for (int i = tid; i < DIN; i += 256) s_x[i] = x[(size_t)b * DIN + i];

    // --- Phase 1: per-thread top-16 of its 64-element stripe ---
    unsigned long long list[NLIST];
    #pragma unroll
    for (int i = 0; i < NLIST; i++) list[i] = 0ULL;

    for (int j = 0; j < DHID / 256; j++) {
        const int h = tid + j * 256;
        unsigned long long key = make_key(row[h], h);
        if (key > list[NLIST - 1]) {
            int p = NLIST - 1;
            #pragma unroll
            for (int q = NLIST - 1; q > 0; q--) {
                if (list[q - 1] < key) { list[q] = list[q - 1]; p = q - 1; }
            }
            list[p] = key;
        }
    }

    // --- Phase 2: block tournament for top-NCAND candidates ---
    int ptr = 0;
    for (int k = 0; k < NCAND; k++) {
        unsigned long long h = (ptr < NLIST) ? list[ptr] : 0ULL;
        unsigned long long m = h;
        #pragma unroll
        for (int off = 16; off > 0; off >>= 1) {
            unsigned long long o = __shfl_down_sync(0xFFFFFFFFu, m, off);
            if (o > m) m = o;
        }
        if (lane == 0) s_wmax[wid] = m;
        __syncthreads();
        if (tid == 0) {
            unsigned long long gm = s_wmax[0];
            #pragma unroll
            for (int w = 1; w < 8; w++) if (s_wmax[w] > gm) gm = s_wmax[w];
            s_sel = gm;
            s_cidx[k] = (int)(0xFFFFFFFFu - (unsigned int)gm);
        }
        __syncthreads();
        if (h == s_sel) ptr++;
    }

    // --- Phase 3: dual rescore, one thread per candidate, ascending k ---
    float lo_acc = 0.f, hi_acc = 0.f;      // ref-chain blocks (512, 256)
    float ex_hi = 0.f, ex_lo = 0.f;        // exact compensated
    for (int ch = 0; ch < NCHUNK; ch++) {
        for (int q = tid; q < NCAND * (DCHUNK / 4); q += 256) {
            const int c  = q / (DCHUNK / 4);
            const int kq = q % (DCHUNK / 4);
            const float4 v = *(const float4*)&W_enc[(size_t)s_cidx[c] * DIN
                                                    + ch * DCHUNK + kq * 4];
            s_w[c][kq * 4 + 0] = v.x;
            s_w[c][kq * 4 + 1] = v.y;
            s_w[c][kq * 4 + 2] = v.z;
            s_w[c][kq * 4 + 3] = v.w;
        }
        __syncthreads();
        if (tid < NCAND) {
            if (ch * DCHUNK < KSPLIT) {
                #pragma unroll 4
                for (int kk = 0; kk < DCHUNK; kk++) {
                    const float xv = s_x[ch * DCHUNK + kk];
                    const float wv = s_w[tid][kk];
                    lo_acc = __fmaf_rn(xv, wv, lo_acc);
                    const float p = __fmul_rn(xv, wv);
                    const float e = __fmaf_rn(xv, wv, -p);
                    float s, err;
                    two_sum(ex_hi, p, s, err);
                    ex_hi = s;
                    ex_lo = __fadd_rn(ex_lo, __fadd_rn(e, err));
                }
            } else {
                #pragma unroll 4
                for (int kk = 0; kk < DCHUNK; kk++) {
                    const float xv = s_x[ch * DCHUNK + kk];
                    const float wv = s_w[tid][kk];
                    hi_acc = __fmaf_rn(xv, wv, hi_acc);
                    const float p = __fmul_rn(xv, wv);
                    const float e = __fmaf_rn(xv, wv, -p);
                    float s, err;
                    two_sum(ex_hi, p, s, err);
                    ex_hi = s;
                    ex_lo = __fadd_rn(ex_lo, __fadd_rn(e, err));
                }
            }
        }
        __syncthreads();
    }
    if (tid < NCAND) {
        const int idx = s_cidx[tid];
        const float bb = b_enc[idx];
        const float hv = __fadd_rn(__fadd_rn(lo_acc, hi_acc), bb);
        float s, err;
        two_sum(ex_hi, bb, s, err);
        const float ev = __fadd_rn(s, __fadd_rn(ex_lo, err));
        s_hval[tid] = hv;
        s_ekey[tid] = make_key(ev, idx);
        s_hkey[tid] = make_key(hv, idx);
    }
    __syncthreads();

    // --- Phase 4: membership by EXACT rank; order by ref-chain rank ---
    if (tid < NCAND) {
        const unsigned long long ek = s_ekey[tid];
        int erank = 0;
        #pragma unroll
        for (int j = 0; j < NCAND; j++) erank += (s_ekey[j] > ek) ? 1 : 0;
        s_member[tid] = (erank < TOPK) ? 1 : 0;
    }
    __syncthreads();
    if (tid < NCAND && s_member[tid]) {
        const unsigned long long hk = s_hkey[tid];
        const int idx = s_cidx[tid];
        int hrank = 0;
        #pragma unroll
        for (int j = 0; j < NCAND; j++)
            if (s_member[j]) hrank += (s_hkey[j] > hk) ? 1 : 0;
        const float rv = fmaxf(s_hval[tid], 0.0f);
        if (idxout) idxout[(size_t)b * TOPK + hrank] = (float)idx;
        if (sparse) sparse[(size_t)b * DHID + idx] = rv;
        s_val[hrank] = rv;
        s_idx[hrank] = idx;
    }
    __syncthreads();

    // --- Phase 5: decode recon[b,:] = b_dec + sum_j val_j * WdecT[idx_j,:] ---
    for (int i = tid; i < DIN; i += 256) {
        float acc = b_dec[i];
        #pragma unroll
        for (int j = 0; j < TOPK; j++)
            acc = fmaf(s_val[j], g_WdecT[(size_t)s_idx[j] * DIN + i], acc);
        recon[(size_t)b * DIN + i] = acc;
    }
}

// ---------------------------------------------------------------------------
// Launch
// ---------------------------------------------------------------------------
extern "C" void kernel_launch(void* const* d_in, const int* in_sizes, int n_in,
                              void* d_out, int out_size) {
    const float* x     = (const float*)d_in[0];
    const float* W_enc = (const float*)d_in[1];
    const float* b_enc = (const float*)d_in[2];
    const float* W_dec = (const float*)d_in[3];
    const float* b_dec = (const float*)d_in[4];
    float* out = (float*)d_out;

    const long long n_recon  = (long long)B_ROWS * DIN;
    const long long n_sparse = (long long)B_ROWS * DHID;
    const long long n_idx    = (long long)B_ROWS * TOPK;
    const long long osz = (long long)out_size;

    float* recon  = out;
    float* sparse = (osz >= n_recon + n_sparse)         ? out + n_recon            : nullptr;
    float* idxo   = (osz >= n_recon + n_sparse + n_idx) ? out + n_recon + n_sparse : nullptr;

    zero_kernel<<<4096, 256>>>(out, osz);
    transpose_kernel<<<dim3(DHID / 32, DIN / 32), dim3(32, 8)>>>(W_dec);
    gemm_tf32_kernel<<<dim3(DHID / BN, B_ROWS / BM), 256>>>(x, W_enc, b_enc);
    topk_rescore_decode_kernel<<<B_ROWS, 256>>>(x, W_enc, b_enc, b_dec,
                                                recon, sparse, idxo);
}